// round 8
// baseline (speedup 1.0000x reference)
#include <cuda_runtime.h>
#include <cstddef>

static constexpr int N_UNITS = 16384;
static constexpr int K_TOP   = 655;
static constexpr int THREADS = 512;
static constexpr int NWARPS  = THREADS / 32;             // 16
static constexpr int VPT4    = N_UNITS / (THREADS * 4);  // float4 vectors per thread = 8
static constexpr int KPT     = VPT4 * 4;                 // keys per thread = 32

__device__ float g_boost[N_UNITS];

__global__ void boost_kernel(const float* __restrict__ duty, int n, float targetDensity) {
    int i = blockIdx.x * blockDim.x + threadIdx.x;
    if (i < n) g_boost[i] = expf(targetDensity - duty[i]);
}

// Order-preserving float -> uint32 map (total order, larger float -> larger key).
__device__ __forceinline__ unsigned mono(float f) {
    unsigned u = __float_as_uint(f);
    return (u & 0x80000000u) ? ~u : (u | 0x80000000u);
}

__global__ __launch_bounds__(THREADS, 2) void kwinners_kernel(
    const float* __restrict__ x, float* __restrict__ out)
{
    __shared__ unsigned h0[NWARPS][256];   // 16 KB: warp-private level-0 histograms
    __shared__ unsigned hl[3][256];        // 3 KB: levels 1..3
    __shared__ unsigned warpTot[8];
    __shared__ unsigned sh_prefix;
    __shared__ int sh_k;

    const int tid  = threadIdx.x;
    const int wid  = tid >> 5;
    const int lane = tid & 31;
    const size_t rowOff = (size_t)blockIdx.x * N_UNITS;
    const float4* __restrict__ xr = (const float4*)(x + rowOff);
    const float4* __restrict__ br = (const float4*)g_boost;

    // ---- Clear all histogram buffers (no cross-warp ordering needed yet) ----
    #pragma unroll
    for (int j = 0; j < 8; j++) h0[wid][lane + 32 * j] = 0u;     // own warp's copy
    #pragma unroll
    for (int j = tid; j < 3 * 256; j += THREADS) ((unsigned*)hl)[j] = 0u;
    if (tid == 0) { sh_prefix = 0u; sh_k = K_TOP; }
    __syncwarp();   // order this warp's h0 clear before its own atomics

    // ---- Load row, apply boost, build level-0 histogram under load latency ----
    unsigned key[KPT];
    unsigned* h = h0[wid];
    #pragma unroll
    for (int i = 0; i < VPT4; i++) {
        int v = tid + THREADS * i;
        float4 xv = __ldcs(&xr[v]);     // read-once: evict-first
        float4 bv = __ldg(&br[v]);      // reused across CTAs: keep cached
        unsigned k0 = mono(xv.x * bv.x);
        unsigned k1 = mono(xv.y * bv.y);
        unsigned k2 = mono(xv.z * bv.z);
        unsigned k3 = mono(xv.w * bv.w);
        key[4*i + 0] = k0;  atomicAdd(&h[k0 >> 24], 1u);
        key[4*i + 1] = k1;  atomicAdd(&h[k1 >> 24], 1u);
        key[4*i + 2] = k2;  atomicAdd(&h[k2 >> 24], 1u);
        key[4*i + 3] = k3;  atomicAdd(&h[k3 >> 24], 1u);
    }
    __syncthreads();   // (1) level-0 histograms complete

    unsigned decided = 0;

    #pragma unroll 1
    for (int level = 0; level < 4; level++) {
        const int shift = 24 - 8 * level;
        const unsigned prefix = sh_prefix;
        const int k = sh_k;

        if (level > 0) {
            // sparse atomics: only keys matching the decided prefix
            unsigned* hb = hl[level - 1];
            #pragma unroll
            for (int j = 0; j < KPT; j++) {
                unsigned kk = key[j];
                if ((kk & decided) == prefix)
                    atomicAdd(&hb[(kk >> shift) & 0xFFu], 1u);
            }
            __syncthreads();   // atomics complete
        }

        // Parallel suffix-sum over 256 bins + pivot decision.
        unsigned v = 0, s = 0;
        if (tid < 256) {
            if (level == 0) {
                #pragma unroll
                for (int w = 0; w < NWARPS; w++) v += h0[w][tid];
            } else {
                v = hl[level - 1][tid];
            }
            s = v;
            #pragma unroll
            for (int off = 1; off < 32; off <<= 1) {
                unsigned t = __shfl_down_sync(0xFFFFFFFFu, s, off);
                if (lane + off < 32) s += t;
            }
            if (lane == 0) warpTot[tid >> 5] = s;
        }
        __syncthreads();
        if (tid < 256) {
            unsigned above = 0;
            #pragma unroll
            for (int w = 0; w < 8; w++)
                if (w > (tid >> 5)) above += warpTot[w];
            unsigned ssum = s + above;                 // count of keys >= start of bin 'tid'
            if (ssum >= (unsigned)k && (ssum - v) < (unsigned)k) {
                sh_prefix = prefix | ((unsigned)tid << shift);
                sh_k = k - (int)(ssum - v);
            }
        }
        decided |= 0xFFu << shift;
        __syncthreads();
    }

    const unsigned T = sh_prefix;   // exact key of the K-th largest element

    // ---- Write binary mask straight from registers ----
    float4* __restrict__ orow = (float4*)(out + rowOff);
    #pragma unroll
    for (int i = 0; i < VPT4; i++) {
        int v = tid + THREADS * i;
        float4 m;
        m.x = (key[4*i + 0] >= T) ? 1.0f : 0.0f;
        m.y = (key[4*i + 1] >= T) ? 1.0f : 0.0f;
        m.z = (key[4*i + 2] >= T) ? 1.0f : 0.0f;
        m.w = (key[4*i + 3] >= T) ? 1.0f : 0.0f;
        __stcs(&orow[v], m);
    }
}

extern "C" void kernel_launch(void* const* d_in, const int* in_sizes, int n_in,
                              void* d_out, int out_size) {
    const float* x    = (const float*)d_in[0];   // (B, N) float32
    const float* duty = (const float*)d_in[1];   // (N,)   float32
    float* out        = (float*)d_out;

    const int n = in_sizes[1];                   // 16384
    const int B = in_sizes[0] / n;               // 4096
    const float targetDensity = (float)K_TOP / (float)n;

    boost_kernel<<<(n + 255) / 256, 256>>>(duty, n, targetDensity);
    kwinners_kernel<<<B, THREADS>>>(x, out);
}